// round 16
// baseline (speedup 1.0000x reference)
#include <cuda_runtime.h>
#include <cuda_fp16.h>
#include <math.h>
#include <stdint.h>

// ---------------- problem constants ----------------
constexpr int NBAG   = 512;
constexpr int MSENT  = 8;
constexpr int TSTEPS = 64;
constexpr int IND    = 360;
constexpr int HID    = 230;
constexpr int OUTD   = 53;
constexpr int ENT    = 8;

constexpr int BB  = NBAG * MSENT;   // 4096
constexpr int H3  = 3 * HID;        // 690
constexpr int H2  = 2 * HID;        // 460
constexpr int NIH = 2 * H3;         // 1380
constexpr long long MM = (long long)TSTEPS * BB;  // 262144

constexpr int KPAD_IN = 384;
constexpr int NPAD_IH = 1408;
constexpr int KPAD_H  = 256;
constexpr int NI_GRU  = 1024;   // interleaved W_hh rows per dir: 32 groups x [r8|z8|n8|pad8]
constexpr int KPAD_W  = 512;
constexpr int NPAD_W  = 512;

constexpr int GRU_BLOCKS = 256; // 8 ntile x 16 m-super x 2 dir; co-resident (<=296)

// ---------------- device scratch ----------------
__device__ float g_bias_ih[NIH];
__device__ float g_bias_hh[2 * H3];
__device__ __half g_XGh[(size_t)MM * NIH];        // x@W_ih^T + b_ih, fp16
__device__ float g_score[TSTEPS * BB];
__device__ float g_wv[(size_t)BB * H2];
__device__ float g_score2[BB];
__device__ volatile unsigned g_bar;               // persistent-kernel grid barrier

// A-side fp16 everywhere. Recurrence weights: fp16 hi+lo split (compounding chain).
// One-shot weights (input proj, word, sent): single fp16.
__device__ __half g_bagF[(size_t)MM * KPAD_IN];
__device__ __half g_WihH[(size_t)NPAD_IH * KPAD_IN];
__device__ __half g_WhhIH[(size_t)2 * NI_GRU * KPAD_H];   // gate-interleaved
__device__ __half g_WhhIL[(size_t)2 * NI_GRU * KPAD_H];
__device__ __half g_WwordH[(size_t)NPAD_W * KPAD_W];
__device__ __half g_WsentH[(size_t)NPAD_W * KPAD_W];
__device__ __half g_OUTF[(size_t)MM * KPAD_W];
__device__ __half g_hA[(size_t)2 * BB * KPAD_H];          // double-buffered hidden state
__device__ __half g_hB[(size_t)2 * BB * KPAD_H];
__device__ __half g_wvF[(size_t)BB * KPAD_W];

// ---------------- helpers ----------------
__device__ __forceinline__ uint32_t smem_u32(const void* p) {
    uint32_t a;
    asm("{ .reg .u64 t; cvta.to.shared.u64 t, %1; cvt.u32.u64 %0, t; }" : "=r"(a) : "l"(p));
    return a;
}
__device__ __forceinline__ void ldm_x4(uint32_t* r, uint32_t addr) {
    asm volatile("ldmatrix.sync.aligned.m8n8.x4.shared.b16 {%0,%1,%2,%3}, [%4];"
                 : "=r"(r[0]), "=r"(r[1]), "=r"(r[2]), "=r"(r[3]) : "r"(addr));
}
__device__ __forceinline__ void mma16816(float* d, const uint32_t* a, const uint32_t* b) {
    asm volatile("mma.sync.aligned.m16n8k16.row.col.f32.f16.f16.f32 "
                 "{%0,%1,%2,%3}, {%4,%5,%6,%7}, {%8,%9}, {%0,%1,%2,%3};"
                 : "+f"(d[0]), "+f"(d[1]), "+f"(d[2]), "+f"(d[3])
                 : "r"(a[0]), "r"(a[1]), "r"(a[2]), "r"(a[3]), "r"(b[0]), "r"(b[1]));
}
__device__ __forceinline__ void cp_async16(uint32_t saddr, const void* gaddr) {
    asm volatile("cp.async.cg.shared.global [%0], [%1], 16;" :: "r"(saddr), "l"(gaddr));
}
#define CP_COMMIT() asm volatile("cp.async.commit_group;" ::: "memory")
#define CP_WAIT0()  asm volatile("cp.async.wait_group 0;" ::: "memory")

// BK = 64: rows of 128B data padded to 144B (bank-stride 36 mod 32 = 4 -> conflict-free).
constexpr int TPAD    = 144;
constexpr int TILE_SM = 128 * TPAD;        // 18432
constexpr int BUFSET  = 3 * TILE_SM;       // 55296 (Af, Bh, Bl) 2-pass (recurrence)
constexpr int SMEM_GEMM = 2 * BUFSET;      // 110592 -> 2 CTAs = 221 KB
constexpr int BUFSET1 = 2 * TILE_SM;       // 36864 (Af, Bh) single-pass
constexpr int SMEM_GEMM1 = 2 * BUFSET1;    // 73728

#define LOAD_CHUNK(dst, off)                                        \
    do {                                                            \
        cp_async16((dst),                    srcA  + (off));        \
        cp_async16((dst) + 64,               srcA  + (off) + 32);   \
        cp_async16((dst) + TILE_SM,          srcBh + (off));        \
        cp_async16((dst) + TILE_SM + 64,     srcBh + (off) + 32);   \
        cp_async16((dst) + 2 * TILE_SM,      srcBl + (off));        \
        cp_async16((dst) + 2 * TILE_SM + 64, srcBl + (off) + 32);   \
    } while (0)

#define LOAD_CHUNK1(dst, off)                                       \
    do {                                                            \
        cp_async16((dst),                    srcA  + (off));        \
        cp_async16((dst) + 64,               srcA  + (off) + 32);   \
        cp_async16((dst) + TILE_SM,          srcBh + (off));        \
        cp_async16((dst) + TILE_SM + 64,     srcBh + (off) + 32);   \
    } while (0)

// ---------------- single-pass fp16 GEMM: C(half) = Af @ Bh^T + bias ----------------
__global__ void __launch_bounds__(512, 2)
gemm_f16s(const __half* __restrict__ Af, const __half* __restrict__ Bh,
          const float* __restrict__ bias, __half* __restrict__ C,
          int N, int ldc, int Kpad, int nit)
{
    extern __shared__ __align__(16) unsigned char sm[];

    int tid = threadIdx.x;
    int lane = tid & 31, wid = tid >> 5;
    int wm = wid >> 2, wn = wid & 3;

    int m0 = blockIdx.y * 128, n0 = blockIdx.x * 128;

    int r0 = tid >> 2, c4 = tid & 3;
    const __half* srcA  = Af + (size_t)(m0 + r0) * Kpad + c4 * 8;
    const __half* srcBh = Bh + (size_t)(n0 + r0) * Kpad + c4 * 8;

    uint32_t smb = smem_u32(sm);
    uint32_t sdst = smb + r0 * TPAD + c4 * 16;

    float acc[2][4][4];
    #pragma unroll
    for (int i = 0; i < 2; i++)
        #pragma unroll
        for (int j = 0; j < 4; j++)
            #pragma unroll
            for (int q = 0; q < 4; q++) acc[i][j][q] = 0.f;

    int arow = (lane & 7) + (((lane >> 3) & 1) << 3);
    int acolb = ((lane >> 4) & 1) * 16;
    uint32_t aBase0 = smb + (wm * 32 + arow) * TPAD + acolb;
    int brow = (lane & 7) + (((lane >> 4) & 1) << 3);
    int bcolb = ((lane >> 3) & 1) * 16;
    uint32_t bhBase0 = smb + TILE_SM + (wn * 32 + brow) * TPAD + bcolb;

    LOAD_CHUNK1(sdst, 0);
    CP_COMMIT();

    int cur = 0;
    for (int kc = 0; kc < nit; kc++) {
        CP_WAIT0();
        __syncthreads();

        if (kc + 1 < nit) {
            LOAD_CHUNK1(sdst + (cur ^ 1) * BUFSET1, (kc + 1) * 64);
            CP_COMMIT();
        }

        uint32_t aBase  = aBase0  + cur * BUFSET1;
        uint32_t bhBase = bhBase0 + cur * BUFSET1;
        #pragma unroll
        for (int s = 0; s < 4; s++) {
            uint32_t af[2][4], bh2[2][4];
            #pragma unroll
            for (int i = 0; i < 2; i++)
                ldm_x4(af[i], aBase + i * 16 * TPAD + s * 32);
            #pragma unroll
            for (int jj = 0; jj < 2; jj++)
                ldm_x4(bh2[jj], bhBase + jj * 16 * TPAD + s * 32);
            #pragma unroll
            for (int i = 0; i < 2; i++)
                #pragma unroll
                for (int j = 0; j < 4; j++)
                    mma16816(acc[i][j], af[i], &bh2[j >> 1][(j & 1) * 2]);
        }
        cur ^= 1;
    }

    int qrow = lane >> 2, qcol = (lane & 3) * 2;
    #pragma unroll
    for (int i = 0; i < 2; i++) {
        #pragma unroll
        for (int j = 0; j < 4; j++) {
            int gc = n0 + wn * 32 + j * 8 + qcol;
            #pragma unroll
            for (int half = 0; half < 2; half++) {
                int gr = m0 + wm * 32 + i * 16 + qrow + half * 8;
                if (gc + 1 < N) {
                    __half2 hv;
                    hv.x = __float2half(acc[i][j][half * 2 + 0] + bias[gc]);
                    hv.y = __float2half(acc[i][j][half * 2 + 1] + bias[gc + 1]);
                    *(__half2*)(C + (size_t)gr * ldc + gc) = hv;
                }
            }
        }
    }
}

// ---------------- persistent recurrence: all 64 GRU steps in one launch ----------------
// 256 blocks: bid = nt(8) | mt2(16) | d(2). Each block: 2 M-tiles of 128 per step.
// B = gate-interleaved W_hh hi+lo (2-pass). Software grid barrier between steps.
__global__ void __launch_bounds__(512, 2)
gemm_gru_persist(const float* __restrict__ bias_hh)
{
    extern __shared__ __align__(16) unsigned char sm[];

    int tid = threadIdx.x;
    int lane = tid & 31, wid = tid >> 5;
    int wm = wid >> 2, wn = wid & 3;

    int bid = blockIdx.x;
    int nt  = bid & 7;
    int mt2 = (bid >> 3) & 15;
    int d   = bid >> 7;

    int n0 = nt * 128;
    int r0 = tid >> 2, c4 = tid & 3;

    uint32_t smb = smem_u32(sm);
    uint32_t sdst = smb + r0 * TPAD + c4 * 16;

    int arow = (lane & 7) + (((lane >> 3) & 1) << 3);
    int acolb = ((lane >> 4) & 1) * 16;
    uint32_t aBase0 = smb + (wm * 32 + arow) * TPAD + acolb;
    int brow = (lane & 7) + (((lane >> 4) & 1) << 3);
    int bcolb = ((lane >> 3) & 1) * 16;
    uint32_t bhBase0 = smb + TILE_SM + (wn * 32 + brow) * TPAD + bcolb;

    const __half* srcBh = g_WhhIH + ((size_t)d * NI_GRU + n0 + r0) * KPAD_H + c4 * 8;
    const __half* srcBl = g_WhhIL + ((size_t)d * NI_GRU + n0 + r0) * KPAD_H + c4 * 8;

    int qrow = lane >> 2, qcol = (lane & 3) * 2;
    int kb = (nt * 4 + wn) * 8 + qcol;
    float2 bhr = {0.f, 0.f}, bhz = {0.f, 0.f}, bhn = {0.f, 0.f};
    if (kb < HID) {
        const float* bh_base = bias_hh + d * H3;
        bhr = *(const float2*)(bh_base + kb);
        bhz = *(const float2*)(bh_base + HID + kb);
        bhn = *(const float2*)(bh_base + 2 * HID + kb);
    }

    for (int s = 0; s < TSTEPS; s++) {
        const __half* hIn  = (s & 1) ? g_hB : g_hA;
        __half* hOut       = (s & 1) ? g_hA : g_hB;
        const __half* Afd  = hIn + (size_t)d * BB * KPAD_H;
        int t_eff = d ? (TSTEPS - 1 - s) : s;

        #pragma unroll 1
        for (int mt = 0; mt < 2; mt++) {
            int m0 = (mt2 * 2 + mt) * 128;
            const __half* srcA = Afd + (size_t)(m0 + r0) * KPAD_H + c4 * 8;

            float acc[2][3][4];
            #pragma unroll
            for (int i = 0; i < 2; i++)
                #pragma unroll
                for (int j = 0; j < 3; j++)
                    #pragma unroll
                    for (int q = 0; q < 4; q++) acc[i][j][q] = 0.f;

            constexpr int nit = KPAD_H / 64;   // 4
            LOAD_CHUNK(sdst, 0);
            CP_COMMIT();

            int cur = 0;
            for (int kc = 0; kc < nit; kc++) {
                CP_WAIT0();
                __syncthreads();

                if (kc + 1 < nit) {
                    LOAD_CHUNK(sdst + (cur ^ 1) * BUFSET, (kc + 1) * 64);
                    CP_COMMIT();
                }

                uint32_t aBase  = aBase0  + cur * BUFSET;
                uint32_t bhBase = bhBase0 + cur * BUFSET;
                #pragma unroll
                for (int si = 0; si < 4; si++) {
                    uint32_t af[2][4], bh2[2][4], bl2[2][4];
                    #pragma unroll
                    for (int i = 0; i < 2; i++)
                        ldm_x4(af[i], aBase + i * 16 * TPAD + si * 32);
                    #pragma unroll
                    for (int jj = 0; jj < 2; jj++) {
                        ldm_x4(bh2[jj], bhBase + jj * 16 * TPAD + si * 32);
                        ldm_x4(bl2[jj], bhBase + TILE_SM + jj * 16 * TPAD + si * 32);
                    }
                    // jj slots 0..2 only (3 = pad)
                    #pragma unroll
                    for (int i = 0; i < 2; i++)
                        #pragma unroll
                        for (int j = 0; j < 3; j++)
                            mma16816(acc[i][j], af[i], &bh2[j >> 1][(j & 1) * 2]);
                    #pragma unroll
                    for (int i = 0; i < 2; i++)
                        #pragma unroll
                        for (int j = 0; j < 3; j++)
                            mma16816(acc[i][j], af[i], &bl2[j >> 1][(j & 1) * 2]);
                }
                cur ^= 1;
            }

            // ---- fused GRU gate epilogue ----
            if (kb < HID) {
                #pragma unroll
                for (int i = 0; i < 2; i++) {
                    #pragma unroll
                    for (int half = 0; half < 2; half++) {
                        int b = m0 + wm * 32 + i * 16 + qrow + half * 8;
                        const __half* xg = g_XGh + ((size_t)t_eff * BB + b) * NIH + d * H3;
                        float2 xr = __half22float2(*(const __half2*)(xg + kb));
                        float2 xz = __half22float2(*(const __half2*)(xg + HID + kb));
                        float2 xn = __half22float2(*(const __half2*)(xg + 2 * HID + kb));
                        size_t hoff = ((size_t)d * BB + b) * KPAD_H + kb;
                        float2 hp = __half22float2(*(const __half2*)(hIn + hoff));

                        float gr0 = acc[i][0][half * 2 + 0] + bhr.x;
                        float gr1 = acc[i][0][half * 2 + 1] + bhr.y;
                        float gz0 = acc[i][1][half * 2 + 0] + bhz.x;
                        float gz1 = acc[i][1][half * 2 + 1] + bhz.y;
                        float gn0 = acc[i][2][half * 2 + 0] + bhn.x;
                        float gn1 = acc[i][2][half * 2 + 1] + bhn.y;

                        float rr0 = 1.f / (1.f + __expf(-(xr.x + gr0)));
                        float rr1 = 1.f / (1.f + __expf(-(xr.y + gr1)));
                        float zz0 = 1.f / (1.f + __expf(-(xz.x + gz0)));
                        float zz1 = 1.f / (1.f + __expf(-(xz.y + gz1)));
                        float nn0 = tanhf(xn.x + rr0 * gn0);
                        float nn1 = tanhf(xn.y + rr1 * gn1);
                        float h0 = (1.f - zz0) * nn0 + zz0 * hp.x;
                        float h1 = (1.f - zz1) * nn1 + zz1 * hp.y;

                        __half2 oh; oh.x = __float2half(h0); oh.y = __float2half(h1);
                        *(__half2*)(hOut + hoff) = oh;
                        size_t oo = ((size_t)t_eff * BB + b) * KPAD_W + (size_t)d * HID + kb;
                        *(__half2*)(g_OUTF + oo) = oh;
                    }
                }
            }
        }

        // ---- grid barrier: writes of step s visible before step s+1 reads ----
        __threadfence();
        __syncthreads();
        if (tid == 0) {
            atomicAdd((unsigned*)&g_bar, 1u);
            unsigned target = (unsigned)GRU_BLOCKS * (unsigned)(s + 1);
            while (g_bar < target) { }
            __threadfence();
        }
        __syncthreads();
    }
}

// ---------------- single-pass fp16 GEMM with fused score epilogue ----------------
__global__ void __launch_bounds__(512, 2)
gemm_score(const __half* __restrict__ Af, const __half* __restrict__ Bh,
           const float* __restrict__ bias, const float* __restrict__ proj,
           float* __restrict__ score, int Nact, int Kpad, int nit, int nbt)
{
    extern __shared__ __align__(16) unsigned char sm[];

    int tid = threadIdx.x;
    int lane = tid & 31, wid = tid >> 5;
    int wm = wid >> 2, wn = wid & 3;
    int m0 = blockIdx.x * 128;

    int r0 = tid >> 2, c4 = tid & 3;
    const __half* srcA = Af + (size_t)(m0 + r0) * Kpad + c4 * 8;

    uint32_t smb = smem_u32(sm);
    uint32_t sdst = smb + r0 * TPAD + c4 * 16;

    int arow = (lane & 7) + (((lane >> 3) & 1) << 3);
    int acolb = ((lane >> 4) & 1) * 16;
    uint32_t aBase0 = smb + (wm * 32 + arow) * TPAD + acolb;
    int brow = (lane & 7) + (((lane >> 4) & 1) << 3);
    int bcolb = ((lane >> 3) & 1) * 16;
    uint32_t bhBase0 = smb + TILE_SM + (wn * 32 + brow) * TPAD + bcolb;

    int qrow = lane >> 2, qcol = (lane & 3) * 2;
    float sacc[2][2] = {{0.f, 0.f}, {0.f, 0.f}};

    for (int nb = 0; nb < nbt; nb++) {
        int n0 = nb * 128;
        const __half* srcBh = Bh + (size_t)(n0 + r0) * Kpad + c4 * 8;

        float acc[2][4][4];
        #pragma unroll
        for (int i = 0; i < 2; i++)
            #pragma unroll
            for (int j = 0; j < 4; j++)
                #pragma unroll
                for (int q = 0; q < 4; q++) acc[i][j][q] = 0.f;

        __syncthreads();   // all warps done with previous nb's smem

        LOAD_CHUNK1(sdst, 0);
        CP_COMMIT();

        int cur = 0;
        for (int kc = 0; kc < nit; kc++) {
            CP_WAIT0();
            __syncthreads();

            if (kc + 1 < nit) {
                LOAD_CHUNK1(sdst + (cur ^ 1) * BUFSET1, (kc + 1) * 64);
                CP_COMMIT();
            }

            uint32_t aBase  = aBase0  + cur * BUFSET1;
            uint32_t bhBase = bhBase0 + cur * BUFSET1;
            #pragma unroll
            for (int s = 0; s < 4; s++) {
                uint32_t af[2][4], bh2[2][4];
                #pragma unroll
                for (int i = 0; i < 2; i++)
                    ldm_x4(af[i], aBase + i * 16 * TPAD + s * 32);
                #pragma unroll
                for (int jj = 0; jj < 2; jj++)
                    ldm_x4(bh2[jj], bhBase + jj * 16 * TPAD + s * 32);
                #pragma unroll
                for (int i = 0; i < 2; i++)
                    #pragma unroll
                    for (int j = 0; j < 4; j++)
                        mma16816(acc[i][j], af[i], &bh2[j >> 1][(j & 1) * 2]);
            }
            cur ^= 1;
        }

        #pragma unroll
        for (int i = 0; i < 2; i++) {
            #pragma unroll
            for (int j = 0; j < 4; j++) {
                int gc = n0 + wn * 32 + j * 8 + qcol;
                #pragma unroll
                for (int half = 0; half < 2; half++) {
                    if (gc < Nact)
                        sacc[i][half] += tanhf(acc[i][j][half * 2 + 0] + bias[gc]) * proj[gc];
                    if (gc + 1 < Nact)
                        sacc[i][half] += tanhf(acc[i][j][half * 2 + 1] + bias[gc + 1]) * proj[gc + 1];
                }
            }
        }
    }

    #pragma unroll
    for (int i = 0; i < 2; i++)
        #pragma unroll
        for (int half = 0; half < 2; half++) {
            float v = sacc[i][half];
            v += __shfl_xor_sync(0xffffffffu, v, 1);
            v += __shfl_xor_sync(0xffffffffu, v, 2);
            sacc[i][half] = v;
        }

    __syncthreads();
    float* sred = (float*)sm;
    if ((lane & 3) == 0) {
        #pragma unroll
        for (int i = 0; i < 2; i++)
            #pragma unroll
            for (int half = 0; half < 2; half++) {
                int rl = wm * 32 + i * 16 + half * 8 + qrow;
                sred[rl * 4 + wn] = sacc[i][half];
            }
    }
    __syncthreads();
    if (tid < 128) {
        float s = sred[tid * 4] + sred[tid * 4 + 1] + sred[tid * 4 + 2] + sred[tid * 4 + 3];
        score[m0 + tid] = s;
    }
}

// ---------------- conversion / prep kernels ----------------
__device__ __forceinline__ void split_f16(float v, __half* H, __half* L, size_t i) {
    __half h = __float2half(v);
    H[i] = h;
    L[i] = __float2half(v - __half2float(h));
}

__global__ void k_zero(float* p, long long n) {
    long long i = (long long)blockIdx.x * blockDim.x + threadIdx.x;
    if (i < n) p[i] = 0.f;
}
__global__ void k_zero_h2(uint32_t* a, uint32_t* b, int nw) {
    int i = blockIdx.x * 256 + threadIdx.x;
    if (i < nw) { a[i] = 0u; b[i] = 0u; }
    if (i == 0) g_bar = 0u;          // reset persistent-kernel barrier each launch
}

__global__ void k_conv_wih(const float* __restrict__ Wf, const float* __restrict__ Wr) {
    int idx = blockIdx.x * 256 + threadIdx.x;
    if (idx >= NIH * IND) return;
    int n = idx / IND, k = idx % IND;
    float v = (n < H3) ? Wf[(size_t)n * IND + k] : Wr[(size_t)(n - H3) * IND + k];
    g_WihH[(size_t)n * KPAD_IN + k] = __float2half(v);
}

constexpr int CW_WHH = 2 * H3 * HID;
constexpr int CW_WW  = H2 * H2;
constexpr int CW_TOT = CW_WHH + 2 * CW_WW + NIH + 2 * H3;
__global__ void k_conv_rest(const float* __restrict__ Whf, const float* __restrict__ Whr,
                            const float* __restrict__ Ww, const float* __restrict__ Ws,
                            const float* __restrict__ bif, const float* __restrict__ bir,
                            const float* __restrict__ bhf, const float* __restrict__ bhr) {
    int idx = blockIdx.x * 256 + threadIdx.x;
    if (idx < CW_WHH) {
        int d = idx / (H3 * HID), r = idx % (H3 * HID);
        int n = r / HID, k = r % HID;       // n = gate*HID + kk
        int gate = n / HID;                  // 0,1,2
        int kk = n % HID;
        int c = (kk >> 3) * 32 + gate * 8 + (kk & 7);   // interleaved row
        const float* W = d ? Whr : Whf;
        split_f16(W[(size_t)n * HID + k], g_WhhIH, g_WhhIL,
                  ((size_t)d * NI_GRU + c) * KPAD_H + k);
        return;
    }
    idx -= CW_WHH;
    if (idx < CW_WW) {
        int n = idx / H2, k = idx % H2;
        g_WwordH[(size_t)n * KPAD_W + k] = __float2half(Ww[(size_t)k * H2 + n]);
        return;
    }
    idx -= CW_WW;
    if (idx < CW_WW) {
        int n = idx / H2, k = idx % H2;
        g_WsentH[(size_t)n * KPAD_W + k] = __float2half(Ws[(size_t)k * H2 + n]);
        return;
    }
    idx -= CW_WW;
    if (idx < NIH) { g_bias_ih[idx] = (idx < H3) ? bif[idx] : bir[idx - H3]; return; }
    idx -= NIH;
    if (idx < 2 * H3) g_bias_hh[idx] = (idx < H3) ? bhf[idx] : bhr[idx - H3];
}

__global__ void k_conv_bag(const float* __restrict__ bag) {
    size_t idx = (size_t)blockIdx.x * 256 + threadIdx.x;   // over MM * 90 (float4 groups)
    if (idx >= (size_t)MM * (IND / 4)) return;
    int j = (int)(idx % (IND / 4));
    size_t m = idx / (IND / 4);
    int tt = (int)(m >> 12), b = (int)(m & 4095);
    float4 v = *(const float4*)(bag + ((size_t)b * TSTEPS + tt) * IND + 4 * j);
    __half2 h0; h0.x = __float2half(v.x); h0.y = __float2half(v.y);
    __half2 h1; h1.x = __float2half(v.z); h1.y = __float2half(v.w);
    size_t o = m * KPAD_IN + 4 * j;
    *(__half2*)(g_bagF + o)     = h0;
    *(__half2*)(g_bagF + o + 2) = h1;
}

// ---------------- fused softmax-over-t + word_vec ----------------
__global__ void k_word_attn() {
    int b = blockIdx.x;
    int tid = threadIdx.x;
    __shared__ float sh[TSTEPS];
    __shared__ float al[TSTEPS];
    if (tid < TSTEPS) {
        float v = g_score[tid * BB + b];
        al[tid] = v; sh[tid] = v;
    }
    __syncthreads();
    #pragma unroll
    for (int o = 32; o; o >>= 1) {
        if (tid < o) sh[tid] = fmaxf(sh[tid], sh[tid + o]);
        __syncthreads();
    }
    float mx = sh[0];
    __syncthreads();
    if (tid < TSTEPS) {
        float e = __expf(al[tid] - mx);
        al[tid] = e; sh[tid] = e;
    }
    __syncthreads();
    #pragma unroll
    for (int o = 32; o; o >>= 1) {
        if (tid < o) sh[tid] += sh[tid + o];
        __syncthreads();
    }
    float inv = 1.f / sh[0];
    __syncthreads();
    if (tid < TSTEPS) al[tid] *= inv;
    __syncthreads();

    for (int h = tid; h < H2; h += blockDim.x) {
        float acc = 0.f;
        #pragma unroll 8
        for (int t = 0; t < TSTEPS; t++)
            acc += al[t] * __half2float(g_OUTF[((size_t)t * BB + b) * KPAD_W + h]);
        g_wv[(size_t)b * H2 + h] = acc;
        g_wvF[(size_t)b * KPAD_W + h] = __float2half(acc);
    }
}

// ---------------- sentence softmax + weighted sum + FC + scatter ----------------
__global__ void k_sent(const float* __restrict__ fcW, const float* __restrict__ fcb,
                       const int* __restrict__ pairs, float* __restrict__ out) {
    int nb = blockIdx.x;
    __shared__ float beta[MSENT];
    __shared__ float sv[H2];
    if (threadIdx.x == 0) {
        float v[MSENT], mx = -1e30f;
        #pragma unroll
        for (int s = 0; s < MSENT; s++) { v[s] = g_score2[nb * MSENT + s]; mx = fmaxf(mx, v[s]); }
        float sum = 0.f;
        #pragma unroll
        for (int s = 0; s < MSENT; s++) { v[s] = expf(v[s] - mx); sum += v[s]; }
        #pragma unroll
        for (int s = 0; s < MSENT; s++) beta[s] = v[s] / sum;
    }
    __syncthreads();
    for (int h = threadIdx.x; h < H2; h += blockDim.x) {
        float acc = 0.f;
        #pragma unroll
        for (int s = 0; s < MSENT; s++)
            acc += beta[s] * g_wv[((size_t)(nb * MSENT + s)) * H2 + h];
        sv[h] = acc;
    }
    __syncthreads();
    const int* p = pairs + nb * 3;
    int base = ((p[0] * ENT + p[1]) * ENT + p[2]) * OUTD;
    for (int o = threadIdx.x; o < OUTD; o += blockDim.x) {
        float acc = fcb[o];
        for (int h = 0; h < H2; h++) acc += sv[h] * fcW[(size_t)o * H2 + h];
        out[base + o] = acc;
    }
}

// ---------------- launcher ----------------
extern "C" void kernel_launch(void* const* d_in, const int* in_sizes, int n_in,
                              void* d_out, int out_size) {
    const float* bag       = (const float*)d_in[0];
    const float* W_ih_f    = (const float*)d_in[1];
    const float* W_hh_f    = (const float*)d_in[2];
    const float* b_ih_f    = (const float*)d_in[3];
    const float* b_hh_f    = (const float*)d_in[4];
    const float* W_ih_r    = (const float*)d_in[5];
    const float* W_hh_r    = (const float*)d_in[6];
    const float* b_ih_r    = (const float*)d_in[7];
    const float* b_hh_r    = (const float*)d_in[8];
    const float* W_word    = (const float*)d_in[9];
    const float* b_word    = (const float*)d_in[10];
    const float* proj_word = (const float*)d_in[11];
    const float* W_sent    = (const float*)d_in[12];
    const float* b_sent    = (const float*)d_in[13];
    const float* proj_sent = (const float*)d_in[14];
    const float* fc_W      = (const float*)d_in[15];
    const float* fc_b      = (const float*)d_in[16];
    const int*   pairs     = (const int*)d_in[17];
    float* out = (float*)d_out;

    static bool attr_set = false;
    if (!attr_set) {
        cudaFuncSetAttribute(gemm_f16s, cudaFuncAttributeMaxDynamicSharedMemorySize, SMEM_GEMM1);
        cudaFuncSetAttribute(gemm_gru_persist, cudaFuncAttributeMaxDynamicSharedMemorySize, SMEM_GEMM);
        cudaFuncSetAttribute(gemm_score, cudaFuncAttributeMaxDynamicSharedMemorySize, SMEM_GEMM1);
        attr_set = true;
    }

    #define SYMA(p, s) void* p; cudaGetSymbolAddress(&p, s)
    SYMA(pXG, g_XGh);
    SYMA(pScore, g_score);
    SYMA(pWv, g_wv);
    SYMA(pScore2, g_score2);
    SYMA(pBih, g_bias_ih); SYMA(pBhh, g_bias_hh);
    SYMA(pBagF, g_bagF);
    SYMA(pWihH, g_WihH);
    SYMA(pWwH, g_WwordH);
    SYMA(pWsH, g_WsentH);
    SYMA(pOF, g_OUTF);
    SYMA(phA, g_hA); SYMA(phB, g_hB);
    SYMA(pwvF, g_wvF);
    #undef SYMA

    // ---- prep (3 launches), then input GEMM as launch #4 (ncu capture slot) ----
    k_conv_wih<<<(NIH * IND + 255) / 256, 256>>>(W_ih_f, W_ih_r);                       // 1
    k_conv_rest<<<(CW_TOT + 255) / 256, 256>>>(W_hh_f, W_hh_r, W_word, W_sent,          // 2
                                               b_ih_f, b_ih_r, b_hh_f, b_hh_r);
    {
        long long n = MM * (IND / 4);                                                   // 3
        k_conv_bag<<<(unsigned)((n + 255) / 256), 256>>>(bag);
    }
    {
        dim3 g(NPAD_IH / 128, (unsigned)(MM / 128), 1);                                 // 4
        gemm_f16s<<<g, 512, SMEM_GEMM1>>>(
            (const __half*)pBagF, (const __half*)pWihH,
            (const float*)pBih, (__half*)pXG,
            NIH, NIH, KPAD_IN, KPAD_IN / 64);
    }
    {
        int nw = 2 * BB * KPAD_H / 2;                                                   // 5
        k_zero_h2<<<(nw + 255) / 256, 256>>>((uint32_t*)phA, (uint32_t*)phB, nw);
    }
    k_zero<<<(out_size + 255) / 256, 256>>>(out, (long long)out_size);                  // 6

    // ---- GRU recurrence: single persistent launch, 64 steps ----
    gemm_gru_persist<<<GRU_BLOCKS, 512, SMEM_GEMM>>>((const float*)pBhh);

    // ---- word attention: fused GEMM + tanh.proj score, fused softmax+wv ----
    gemm_score<<<(unsigned)(MM / 128), 512, SMEM_GEMM1>>>(
        (const __half*)pOF, (const __half*)pWwH,
        b_word, proj_word, (float*)pScore, H2, KPAD_W, KPAD_W / 64, NPAD_W / 128);
    k_word_attn<<<BB, 256>>>();

    // ---- sentence attention: fused GEMM + score, then softmax+FC+scatter ----
    gemm_score<<<BB / 128, 512, SMEM_GEMM1>>>(
        (const __half*)pwvF, (const __half*)pWsH,
        b_sent, proj_sent, (float*)pScore2, H2, KPAD_W, KPAD_W / 64, NPAD_W / 128);
    k_sent<<<NBAG, 256>>>(fc_W, fc_b, pairs, out);
}

// round 17
// speedup vs baseline: 1.0508x; 1.0508x over previous
#include <cuda_runtime.h>
#include <cuda_fp16.h>
#include <math.h>
#include <stdint.h>

// ---------------- problem constants ----------------
constexpr int NBAG   = 512;
constexpr int MSENT  = 8;
constexpr int TSTEPS = 64;
constexpr int IND    = 360;
constexpr int HID    = 230;
constexpr int OUTD   = 53;
constexpr int ENT    = 8;

constexpr int BB  = NBAG * MSENT;   // 4096
constexpr int H3  = 3 * HID;        // 690
constexpr int H2  = 2 * HID;        // 460
constexpr int NIH = 2 * H3;         // 1380
constexpr long long MM = (long long)TSTEPS * BB;  // 262144

constexpr int KPAD_IN = 384;
constexpr int NPAD_IH = 1408;
constexpr int KPAD_H  = 256;
constexpr int NI_GRU  = 1024;   // interleaved W_hh rows per dir: 32 groups x [r8|z8|n8|pad8]
constexpr int KPAD_W  = 512;
constexpr int NPAD_W  = 512;

// ---------------- device scratch ----------------
__device__ float g_bias_ih[NIH];
__device__ float g_bias_hh[2 * H3];
__device__ __half g_XGh[(size_t)MM * NIH];        // x@W_ih^T + b_ih, fp16
__device__ float g_score[TSTEPS * BB];
__device__ float g_wv[(size_t)BB * H2];
__device__ float g_score2[BB];

// A-side fp16 everywhere. Recurrence weights: fp16 hi+lo split; Bl correction
// applied only to the n gate (tanh path) — r/z sigmoid paths attenuate it.
__device__ __half g_bagF[(size_t)MM * KPAD_IN];
__device__ __half g_WihH[(size_t)NPAD_IH * KPAD_IN];
__device__ __half g_WhhIH[(size_t)2 * NI_GRU * KPAD_H];   // gate-interleaved
__device__ __half g_WhhIL[(size_t)2 * NI_GRU * KPAD_H];
__device__ __half g_WwordH[(size_t)NPAD_W * KPAD_W];
__device__ __half g_WsentH[(size_t)NPAD_W * KPAD_W];
__device__ __half g_OUTF[(size_t)MM * KPAD_W];
__device__ __half g_hA[(size_t)2 * BB * KPAD_H];          // double-buffered hidden state
__device__ __half g_hB[(size_t)2 * BB * KPAD_H];
__device__ __half g_wvF[(size_t)BB * KPAD_W];

// ---------------- helpers ----------------
__device__ __forceinline__ uint32_t smem_u32(const void* p) {
    uint32_t a;
    asm("{ .reg .u64 t; cvta.to.shared.u64 t, %1; cvt.u32.u64 %0, t; }" : "=r"(a) : "l"(p));
    return a;
}
__device__ __forceinline__ void ldm_x4(uint32_t* r, uint32_t addr) {
    asm volatile("ldmatrix.sync.aligned.m8n8.x4.shared.b16 {%0,%1,%2,%3}, [%4];"
                 : "=r"(r[0]), "=r"(r[1]), "=r"(r[2]), "=r"(r[3]) : "r"(addr));
}
__device__ __forceinline__ void mma16816(float* d, const uint32_t* a, const uint32_t* b) {
    asm volatile("mma.sync.aligned.m16n8k16.row.col.f32.f16.f16.f32 "
                 "{%0,%1,%2,%3}, {%4,%5,%6,%7}, {%8,%9}, {%0,%1,%2,%3};"
                 : "+f"(d[0]), "+f"(d[1]), "+f"(d[2]), "+f"(d[3])
                 : "r"(a[0]), "r"(a[1]), "r"(a[2]), "r"(a[3]), "r"(b[0]), "r"(b[1]));
}
__device__ __forceinline__ void cp_async16(uint32_t saddr, const void* gaddr) {
    asm volatile("cp.async.cg.shared.global [%0], [%1], 16;" :: "r"(saddr), "l"(gaddr));
}
#define CP_COMMIT() asm volatile("cp.async.commit_group;" ::: "memory")
#define CP_WAIT0()  asm volatile("cp.async.wait_group 0;" ::: "memory")

// BK = 64: rows of 128B data padded to 144B (bank-stride 36 mod 32 = 4 -> conflict-free).
constexpr int TPAD    = 144;
constexpr int TILE_SM = 128 * TPAD;        // 18432
constexpr int BUFSET  = 3 * TILE_SM;       // 55296 (Af, Bh, Bl) recurrence
constexpr int SMEM_GEMM = 2 * BUFSET;      // 110592 -> 2 CTAs = 221 KB
constexpr int BUFSET1 = 2 * TILE_SM;       // 36864 (Af, Bh) single-pass
constexpr int SMEM_GEMM1 = 2 * BUFSET1;    // 73728

#define LOAD_CHUNK(dst, off)                                        \
    do {                                                            \
        cp_async16((dst),                    srcA  + (off));        \
        cp_async16((dst) + 64,               srcA  + (off) + 32);   \
        cp_async16((dst) + TILE_SM,          srcBh + (off));        \
        cp_async16((dst) + TILE_SM + 64,     srcBh + (off) + 32);   \
        cp_async16((dst) + 2 * TILE_SM,      srcBl + (off));        \
        cp_async16((dst) + 2 * TILE_SM + 64, srcBl + (off) + 32);   \
    } while (0)

#define LOAD_CHUNK1(dst, off)                                       \
    do {                                                            \
        cp_async16((dst),                    srcA  + (off));        \
        cp_async16((dst) + 64,               srcA  + (off) + 32);   \
        cp_async16((dst) + TILE_SM,          srcBh + (off));        \
        cp_async16((dst) + TILE_SM + 64,     srcBh + (off) + 32);   \
    } while (0)

// ---------------- single-pass fp16 GEMM: C(half) = Af @ Bh^T + bias ----------------
__global__ void __launch_bounds__(512, 2)
gemm_f16s(const __half* __restrict__ Af, const __half* __restrict__ Bh,
          const float* __restrict__ bias, __half* __restrict__ C,
          int N, int ldc, int Kpad, int nit)
{
    extern __shared__ __align__(16) unsigned char sm[];

    int tid = threadIdx.x;
    int lane = tid & 31, wid = tid >> 5;
    int wm = wid >> 2, wn = wid & 3;

    int m0 = blockIdx.y * 128, n0 = blockIdx.x * 128;

    int r0 = tid >> 2, c4 = tid & 3;
    const __half* srcA  = Af + (size_t)(m0 + r0) * Kpad + c4 * 8;
    const __half* srcBh = Bh + (size_t)(n0 + r0) * Kpad + c4 * 8;

    uint32_t smb = smem_u32(sm);
    uint32_t sdst = smb + r0 * TPAD + c4 * 16;

    float acc[2][4][4];
    #pragma unroll
    for (int i = 0; i < 2; i++)
        #pragma unroll
        for (int j = 0; j < 4; j++)
            #pragma unroll
            for (int q = 0; q < 4; q++) acc[i][j][q] = 0.f;

    int arow = (lane & 7) + (((lane >> 3) & 1) << 3);
    int acolb = ((lane >> 4) & 1) * 16;
    uint32_t aBase0 = smb + (wm * 32 + arow) * TPAD + acolb;
    int brow = (lane & 7) + (((lane >> 4) & 1) << 3);
    int bcolb = ((lane >> 3) & 1) * 16;
    uint32_t bhBase0 = smb + TILE_SM + (wn * 32 + brow) * TPAD + bcolb;

    LOAD_CHUNK1(sdst, 0);
    CP_COMMIT();

    int cur = 0;
    for (int kc = 0; kc < nit; kc++) {
        CP_WAIT0();
        __syncthreads();

        if (kc + 1 < nit) {
            LOAD_CHUNK1(sdst + (cur ^ 1) * BUFSET1, (kc + 1) * 64);
            CP_COMMIT();
        }

        uint32_t aBase  = aBase0  + cur * BUFSET1;
        uint32_t bhBase = bhBase0 + cur * BUFSET1;
        #pragma unroll
        for (int s = 0; s < 4; s++) {
            uint32_t af[2][4], bh2[2][4];
            #pragma unroll
            for (int i = 0; i < 2; i++)
                ldm_x4(af[i], aBase + i * 16 * TPAD + s * 32);
            #pragma unroll
            for (int jj = 0; jj < 2; jj++)
                ldm_x4(bh2[jj], bhBase + jj * 16 * TPAD + s * 32);
            #pragma unroll
            for (int i = 0; i < 2; i++)
                #pragma unroll
                for (int j = 0; j < 4; j++)
                    mma16816(acc[i][j], af[i], &bh2[j >> 1][(j & 1) * 2]);
        }
        cur ^= 1;
    }

    int qrow = lane >> 2, qcol = (lane & 3) * 2;
    #pragma unroll
    for (int i = 0; i < 2; i++) {
        #pragma unroll
        for (int j = 0; j < 4; j++) {
            int gc = n0 + wn * 32 + j * 8 + qcol;
            #pragma unroll
            for (int half = 0; half < 2; half++) {
                int gr = m0 + wm * 32 + i * 16 + qrow + half * 8;
                if (gc + 1 < N) {
                    __half2 hv;
                    hv.x = __float2half(acc[i][j][half * 2 + 0] + bias[gc]);
                    hv.y = __float2half(acc[i][j][half * 2 + 1] + bias[gc + 1]);
                    *(__half2*)(C + (size_t)gr * ldc + gc) = hv;
                }
            }
        }
    }
}

// ---------------- recurrence GEMM with fused GRU gate epilogue ----------------
// B = gate-interleaved W_hh (period 32: r8|z8|n8|pad8). jj=3 (pad) MMAs skipped.
// Bh pass: all gates. Bl correction pass: n gate (j=2) ONLY — r/z go through
// sigmoid (slope<=0.25), attenuating weight-rounding error below fp16 A noise.
__global__ void __launch_bounds__(512, 2)
gemm_gru(const __half* __restrict__ hIn, const __half* __restrict__ Bhw,
         const __half* __restrict__ Blw, const float* __restrict__ bias_hh,
         __half* __restrict__ hOut, int step)
{
    extern __shared__ __align__(16) unsigned char sm[];

    int tid = threadIdx.x;
    int lane = tid & 31, wid = tid >> 5;
    int wm = wid >> 2, wn = wid & 3;
    int d = blockIdx.z;

    const __half* Af  = hIn + (size_t)d * BB * KPAD_H;
    const __half* Bhd = Bhw + (size_t)d * NI_GRU * KPAD_H;
    const __half* Bld = Blw + (size_t)d * NI_GRU * KPAD_H;

    int m0 = blockIdx.y * 128, n0 = blockIdx.x * 128;

    int r0 = tid >> 2, c4 = tid & 3;
    const __half* srcA  = Af  + (size_t)(m0 + r0) * KPAD_H + c4 * 8;
    const __half* srcBh = Bhd + (size_t)(n0 + r0) * KPAD_H + c4 * 8;
    const __half* srcBl = Bld + (size_t)(n0 + r0) * KPAD_H + c4 * 8;

    uint32_t smb = smem_u32(sm);
    uint32_t sdst = smb + r0 * TPAD + c4 * 16;

    float acc[2][3][4];
    #pragma unroll
    for (int i = 0; i < 2; i++)
        #pragma unroll
        for (int j = 0; j < 3; j++)
            #pragma unroll
            for (int q = 0; q < 4; q++) acc[i][j][q] = 0.f;

    int arow = (lane & 7) + (((lane >> 3) & 1) << 3);
    int acolb = ((lane >> 4) & 1) * 16;
    uint32_t aBase0 = smb + (wm * 32 + arow) * TPAD + acolb;
    int brow = (lane & 7) + (((lane >> 4) & 1) << 3);
    int bcolb = ((lane >> 3) & 1) * 16;
    uint32_t bhBase0 = smb + TILE_SM + (wn * 32 + brow) * TPAD + bcolb;

    constexpr int nit = KPAD_H / 64;   // 4
    LOAD_CHUNK(sdst, 0);
    CP_COMMIT();

    int cur = 0;
    for (int kc = 0; kc < nit; kc++) {
        CP_WAIT0();
        __syncthreads();

        if (kc + 1 < nit) {
            LOAD_CHUNK(sdst + (cur ^ 1) * BUFSET, (kc + 1) * 64);
            CP_COMMIT();
        }

        uint32_t aBase  = aBase0  + cur * BUFSET;
        uint32_t bhBase = bhBase0 + cur * BUFSET;
        #pragma unroll
        for (int s = 0; s < 4; s++) {
            uint32_t af[2][4], bh2[2][4], bl2[4];
            #pragma unroll
            for (int i = 0; i < 2; i++)
                ldm_x4(af[i], aBase + i * 16 * TPAD + s * 32);
            #pragma unroll
            for (int jj = 0; jj < 2; jj++)
                ldm_x4(bh2[jj], bhBase + jj * 16 * TPAD + s * 32);
            // Bl: only the jj=1 fragment is consumed (n-gate rows 16..23)
            ldm_x4(bl2, bhBase + TILE_SM + 16 * TPAD + s * 32);
            // Bh pass: gates r,z,n (jj slot 3 = pad, skipped)
            #pragma unroll
            for (int i = 0; i < 2; i++)
                #pragma unroll
                for (int j = 0; j < 3; j++)
                    mma16816(acc[i][j], af[i], &bh2[j >> 1][(j & 1) * 2]);
            // Bl pass: n gate only (j=2 -> fragment bl2[0..1])
            #pragma unroll
            for (int i = 0; i < 2; i++)
                mma16816(acc[i][2], af[i], &bl2[0]);
        }
        cur ^= 1;
    }

    // ---- fused GRU gate epilogue ----
    int qrow = lane >> 2, qcol = (lane & 3) * 2;
    int kb = (blockIdx.x * 4 + wn) * 8 + qcol;
    if (kb < HID) {
        int t_eff = d ? (TSTEPS - 1 - step) : step;
        const float* bh_base = bias_hh + d * H3;
        float2 bhr = *(const float2*)(bh_base + kb);
        float2 bhz = *(const float2*)(bh_base + HID + kb);
        float2 bhn = *(const float2*)(bh_base + 2 * HID + kb);

        #pragma unroll
        for (int i = 0; i < 2; i++) {
            #pragma unroll
            for (int half = 0; half < 2; half++) {
                int b = m0 + wm * 32 + i * 16 + qrow + half * 8;
                const __half* xg = g_XGh + ((size_t)t_eff * BB + b) * NIH + d * H3;
                float2 xr = __half22float2(*(const __half2*)(xg + kb));
                float2 xz = __half22float2(*(const __half2*)(xg + HID + kb));
                float2 xn = __half22float2(*(const __half2*)(xg + 2 * HID + kb));
                size_t hoff = ((size_t)d * BB + b) * KPAD_H + kb;
                float2 hp = __half22float2(*(const __half2*)(hIn + hoff));

                float gr0 = acc[i][0][half * 2 + 0] + bhr.x;
                float gr1 = acc[i][0][half * 2 + 1] + bhr.y;
                float gz0 = acc[i][1][half * 2 + 0] + bhz.x;
                float gz1 = acc[i][1][half * 2 + 1] + bhz.y;
                float gn0 = acc[i][2][half * 2 + 0] + bhn.x;
                float gn1 = acc[i][2][half * 2 + 1] + bhn.y;

                float rr0 = 1.f / (1.f + __expf(-(xr.x + gr0)));
                float rr1 = 1.f / (1.f + __expf(-(xr.y + gr1)));
                float zz0 = 1.f / (1.f + __expf(-(xz.x + gz0)));
                float zz1 = 1.f / (1.f + __expf(-(xz.y + gz1)));
                float nn0 = tanhf(xn.x + rr0 * gn0);
                float nn1 = tanhf(xn.y + rr1 * gn1);
                float h0 = (1.f - zz0) * nn0 + zz0 * hp.x;
                float h1 = (1.f - zz1) * nn1 + zz1 * hp.y;

                __half2 oh; oh.x = __float2half(h0); oh.y = __float2half(h1);
                *(__half2*)(hOut + hoff) = oh;
                size_t oo = ((size_t)t_eff * BB + b) * KPAD_W + (size_t)d * HID + kb;
                *(__half2*)(g_OUTF + oo) = oh;
            }
        }
    }
}

// ---------------- single-pass fp16 GEMM with fused score epilogue ----------------
__global__ void __launch_bounds__(512, 2)
gemm_score(const __half* __restrict__ Af, const __half* __restrict__ Bh,
           const float* __restrict__ bias, const float* __restrict__ proj,
           float* __restrict__ score, int Nact, int Kpad, int nit, int nbt)
{
    extern __shared__ __align__(16) unsigned char sm[];

    int tid = threadIdx.x;
    int lane = tid & 31, wid = tid >> 5;
    int wm = wid >> 2, wn = wid & 3;
    int m0 = blockIdx.x * 128;

    int r0 = tid >> 2, c4 = tid & 3;
    const __half* srcA = Af + (size_t)(m0 + r0) * Kpad + c4 * 8;

    uint32_t smb = smem_u32(sm);
    uint32_t sdst = smb + r0 * TPAD + c4 * 16;

    int arow = (lane & 7) + (((lane >> 3) & 1) << 3);
    int acolb = ((lane >> 4) & 1) * 16;
    uint32_t aBase0 = smb + (wm * 32 + arow) * TPAD + acolb;
    int brow = (lane & 7) + (((lane >> 4) & 1) << 3);
    int bcolb = ((lane >> 3) & 1) * 16;
    uint32_t bhBase0 = smb + TILE_SM + (wn * 32 + brow) * TPAD + bcolb;

    int qrow = lane >> 2, qcol = (lane & 3) * 2;
    float sacc[2][2] = {{0.f, 0.f}, {0.f, 0.f}};

    for (int nb = 0; nb < nbt; nb++) {
        int n0 = nb * 128;
        const __half* srcBh = Bh + (size_t)(n0 + r0) * Kpad + c4 * 8;

        float acc[2][4][4];
        #pragma unroll
        for (int i = 0; i < 2; i++)
            #pragma unroll
            for (int j = 0; j < 4; j++)
                #pragma unroll
                for (int q = 0; q < 4; q++) acc[i][j][q] = 0.f;

        __syncthreads();   // all warps done with previous nb's smem

        LOAD_CHUNK1(sdst, 0);
        CP_COMMIT();

        int cur = 0;
        for (int kc = 0; kc < nit; kc++) {
            CP_WAIT0();
            __syncthreads();

            if (kc + 1 < nit) {
                LOAD_CHUNK1(sdst + (cur ^ 1) * BUFSET1, (kc + 1) * 64);
                CP_COMMIT();
            }

            uint32_t aBase  = aBase0  + cur * BUFSET1;
            uint32_t bhBase = bhBase0 + cur * BUFSET1;
            #pragma unroll
            for (int s = 0; s < 4; s++) {
                uint32_t af[2][4], bh2[2][4];
                #pragma unroll
                for (int i = 0; i < 2; i++)
                    ldm_x4(af[i], aBase + i * 16 * TPAD + s * 32);
                #pragma unroll
                for (int jj = 0; jj < 2; jj++)
                    ldm_x4(bh2[jj], bhBase + jj * 16 * TPAD + s * 32);
                #pragma unroll
                for (int i = 0; i < 2; i++)
                    #pragma unroll
                    for (int j = 0; j < 4; j++)
                        mma16816(acc[i][j], af[i], &bh2[j >> 1][(j & 1) * 2]);
            }
            cur ^= 1;
        }

        #pragma unroll
        for (int i = 0; i < 2; i++) {
            #pragma unroll
            for (int j = 0; j < 4; j++) {
                int gc = n0 + wn * 32 + j * 8 + qcol;
                #pragma unroll
                for (int half = 0; half < 2; half++) {
                    if (gc < Nact)
                        sacc[i][half] += tanhf(acc[i][j][half * 2 + 0] + bias[gc]) * proj[gc];
                    if (gc + 1 < Nact)
                        sacc[i][half] += tanhf(acc[i][j][half * 2 + 1] + bias[gc + 1]) * proj[gc + 1];
                }
            }
        }
    }

    #pragma unroll
    for (int i = 0; i < 2; i++)
        #pragma unroll
        for (int half = 0; half < 2; half++) {
            float v = sacc[i][half];
            v += __shfl_xor_sync(0xffffffffu, v, 1);
            v += __shfl_xor_sync(0xffffffffu, v, 2);
            sacc[i][half] = v;
        }

    __syncthreads();
    float* sred = (float*)sm;
    if ((lane & 3) == 0) {
        #pragma unroll
        for (int i = 0; i < 2; i++)
            #pragma unroll
            for (int half = 0; half < 2; half++) {
                int rl = wm * 32 + i * 16 + half * 8 + qrow;
                sred[rl * 4 + wn] = sacc[i][half];
            }
    }
    __syncthreads();
    if (tid < 128) {
        float s = sred[tid * 4] + sred[tid * 4 + 1] + sred[tid * 4 + 2] + sred[tid * 4 + 3];
        score[m0 + tid] = s;
    }
}

// ---------------- conversion / prep kernels ----------------
__device__ __forceinline__ void split_f16(float v, __half* H, __half* L, size_t i) {
    __half h = __float2half(v);
    H[i] = h;
    L[i] = __float2half(v - __half2float(h));
}

__global__ void k_zero(float* p, long long n) {
    long long i = (long long)blockIdx.x * blockDim.x + threadIdx.x;
    if (i < n) p[i] = 0.f;
}
__global__ void k_zero_h2(uint32_t* a, uint32_t* b, int nw) {
    int i = blockIdx.x * 256 + threadIdx.x;
    if (i < nw) { a[i] = 0u; b[i] = 0u; }
}

__global__ void k_conv_wih(const float* __restrict__ Wf, const float* __restrict__ Wr) {
    int idx = blockIdx.x * 256 + threadIdx.x;
    if (idx >= NIH * IND) return;
    int n = idx / IND, k = idx % IND;
    float v = (n < H3) ? Wf[(size_t)n * IND + k] : Wr[(size_t)(n - H3) * IND + k];
    g_WihH[(size_t)n * KPAD_IN + k] = __float2half(v);
}

constexpr int CW_WHH = 2 * H3 * HID;
constexpr int CW_WW  = H2 * H2;
constexpr int CW_TOT = CW_WHH + 2 * CW_WW + NIH + 2 * H3;
__global__ void k_conv_rest(const float* __restrict__ Whf, const float* __restrict__ Whr,
                            const float* __restrict__ Ww, const float* __restrict__ Ws,
                            const float* __restrict__ bif, const float* __restrict__ bir,
                            const float* __restrict__ bhf, const float* __restrict__ bhr) {
    int idx = blockIdx.x * 256 + threadIdx.x;
    if (idx < CW_WHH) {
        int d = idx / (H3 * HID), r = idx % (H3 * HID);
        int n = r / HID, k = r % HID;       // n = gate*HID + kk
        int gate = n / HID;                  // 0,1,2
        int kk = n % HID;
        int c = (kk >> 3) * 32 + gate * 8 + (kk & 7);   // interleaved row
        const float* W = d ? Whr : Whf;
        split_f16(W[(size_t)n * HID + k], g_WhhIH, g_WhhIL,
                  ((size_t)d * NI_GRU + c) * KPAD_H + k);
        return;
    }
    idx -= CW_WHH;
    if (idx < CW_WW) {
        int n = idx / H2, k = idx % H2;
        g_WwordH[(size_t)n * KPAD_W + k] = __float2half(Ww[(size_t)k * H2 + n]);
        return;
    }
    idx -= CW_WW;
    if (idx < CW_WW) {
        int n = idx / H2, k = idx % H2;
        g_WsentH[(size_t)n * KPAD_W + k] = __float2half(Ws[(size_t)k * H2 + n]);
        return;
    }
    idx -= CW_WW;
    if (idx < NIH) { g_bias_ih[idx] = (idx < H3) ? bif[idx] : bir[idx - H3]; return; }
    idx -= NIH;
    if (idx < 2 * H3) g_bias_hh[idx] = (idx < H3) ? bhf[idx] : bhr[idx - H3];
}

__global__ void k_conv_bag(const float* __restrict__ bag) {
    size_t idx = (size_t)blockIdx.x * 256 + threadIdx.x;   // over MM * 90 (float4 groups)
    if (idx >= (size_t)MM * (IND / 4)) return;
    int j = (int)(idx % (IND / 4));
    size_t m = idx / (IND / 4);
    int tt = (int)(m >> 12), b = (int)(m & 4095);
    float4 v = *(const float4*)(bag + ((size_t)b * TSTEPS + tt) * IND + 4 * j);
    __half2 h0; h0.x = __float2half(v.x); h0.y = __float2half(v.y);
    __half2 h1; h1.x = __float2half(v.z); h1.y = __float2half(v.w);
    size_t o = m * KPAD_IN + 4 * j;
    *(__half2*)(g_bagF + o)     = h0;
    *(__half2*)(g_bagF + o + 2) = h1;
}

// ---------------- fused softmax-over-t + word_vec ----------------
__global__ void k_word_attn() {
    int b = blockIdx.x;
    int tid = threadIdx.x;
    __shared__ float sh[TSTEPS];
    __shared__ float al[TSTEPS];
    if (tid < TSTEPS) {
        float v = g_score[tid * BB + b];
        al[tid] = v; sh[tid] = v;
    }
    __syncthreads();
    #pragma unroll
    for (int o = 32; o; o >>= 1) {
        if (tid < o) sh[tid] = fmaxf(sh[tid], sh[tid + o]);
        __syncthreads();
    }
    float mx = sh[0];
    __syncthreads();
    if (tid < TSTEPS) {
        float e = __expf(al[tid] - mx);
        al[tid] = e; sh[tid] = e;
    }
    __syncthreads();
    #pragma unroll
    for (int o = 32; o; o >>= 1) {
        if (tid < o) sh[tid] += sh[tid + o];
        __syncthreads();
    }
    float inv = 1.f / sh[0];
    __syncthreads();
    if (tid < TSTEPS) al[tid] *= inv;
    __syncthreads();

    for (int h = tid; h < H2; h += blockDim.x) {
        float acc = 0.f;
        #pragma unroll 8
        for (int t = 0; t < TSTEPS; t++)
            acc += al[t] * __half2float(g_OUTF[((size_t)t * BB + b) * KPAD_W + h]);
        g_wv[(size_t)b * H2 + h] = acc;
        g_wvF[(size_t)b * KPAD_W + h] = __float2half(acc);
    }
}

// ---------------- sentence softmax + weighted sum + FC + scatter ----------------
__global__ void k_sent(const float* __restrict__ fcW, const float* __restrict__ fcb,
                       const int* __restrict__ pairs, float* __restrict__ out) {
    int nb = blockIdx.x;
    __shared__ float beta[MSENT];
    __shared__ float sv[H2];
    if (threadIdx.x == 0) {
        float v[MSENT], mx = -1e30f;
        #pragma unroll
        for (int s = 0; s < MSENT; s++) { v[s] = g_score2[nb * MSENT + s]; mx = fmaxf(mx, v[s]); }
        float sum = 0.f;
        #pragma unroll
        for (int s = 0; s < MSENT; s++) { v[s] = expf(v[s] - mx); sum += v[s]; }
        #pragma unroll
        for (int s = 0; s < MSENT; s++) beta[s] = v[s] / sum;
    }
    __syncthreads();
    for (int h = threadIdx.x; h < H2; h += blockDim.x) {
        float acc = 0.f;
        #pragma unroll
        for (int s = 0; s < MSENT; s++)
            acc += beta[s] * g_wv[((size_t)(nb * MSENT + s)) * H2 + h];
        sv[h] = acc;
    }
    __syncthreads();
    const int* p = pairs + nb * 3;
    int base = ((p[0] * ENT + p[1]) * ENT + p[2]) * OUTD;
    for (int o = threadIdx.x; o < OUTD; o += blockDim.x) {
        float acc = fcb[o];
        for (int h = 0; h < H2; h++) acc += sv[h] * fcW[(size_t)o * H2 + h];
        out[base + o] = acc;
    }
}

// ---------------- launcher ----------------
extern "C" void kernel_launch(void* const* d_in, const int* in_sizes, int n_in,
                              void* d_out, int out_size) {
    const float* bag       = (const float*)d_in[0];
    const float* W_ih_f    = (const float*)d_in[1];
    const float* W_hh_f    = (const float*)d_in[2];
    const float* b_ih_f    = (const float*)d_in[3];
    const float* b_hh_f    = (const float*)d_in[4];
    const float* W_ih_r    = (const float*)d_in[5];
    const float* W_hh_r    = (const float*)d_in[6];
    const float* b_ih_r    = (const float*)d_in[7];
    const float* b_hh_r    = (const float*)d_in[8];
    const float* W_word    = (const float*)d_in[9];
    const float* b_word    = (const float*)d_in[10];
    const float* proj_word = (const float*)d_in[11];
    const float* W_sent    = (const float*)d_in[12];
    const float* b_sent    = (const float*)d_in[13];
    const float* proj_sent = (const float*)d_in[14];
    const float* fc_W      = (const float*)d_in[15];
    const float* fc_b      = (const float*)d_in[16];
    const int*   pairs     = (const int*)d_in[17];
    float* out = (float*)d_out;

    static bool attr_set = false;
    if (!attr_set) {
        cudaFuncSetAttribute(gemm_f16s, cudaFuncAttributeMaxDynamicSharedMemorySize, SMEM_GEMM1);
        cudaFuncSetAttribute(gemm_gru, cudaFuncAttributeMaxDynamicSharedMemorySize, SMEM_GEMM);
        cudaFuncSetAttribute(gemm_score, cudaFuncAttributeMaxDynamicSharedMemorySize, SMEM_GEMM1);
        attr_set = true;
    }

    #define SYMA(p, s) void* p; cudaGetSymbolAddress(&p, s)
    SYMA(pXG, g_XGh);
    SYMA(pScore, g_score);
    SYMA(pWv, g_wv);
    SYMA(pScore2, g_score2);
    SYMA(pBih, g_bias_ih); SYMA(pBhh, g_bias_hh);
    SYMA(pBagF, g_bagF);
    SYMA(pWihH, g_WihH);
    SYMA(pWhhIH, g_WhhIH); SYMA(pWhhIL, g_WhhIL);
    SYMA(pWwH, g_WwordH);
    SYMA(pWsH, g_WsentH);
    SYMA(pOF, g_OUTF);
    SYMA(phA, g_hA); SYMA(phB, g_hB);
    SYMA(pwvF, g_wvF);
    #undef SYMA

    // ---- prep (3 launches), then input GEMM as launch #4 (ncu capture slot) ----
    k_conv_wih<<<(NIH * IND + 255) / 256, 256>>>(W_ih_f, W_ih_r);                       // 1
    k_conv_rest<<<(CW_TOT + 255) / 256, 256>>>(W_hh_f, W_hh_r, W_word, W_sent,          // 2
                                               b_ih_f, b_ih_r, b_hh_f, b_hh_r);
    {
        long long n = MM * (IND / 4);                                                   // 3
        k_conv_bag<<<(unsigned)((n + 255) / 256), 256>>>(bag);
    }
    {
        dim3 g(NPAD_IH / 128, (unsigned)(MM / 128), 1);                                 // 4
        gemm_f16s<<<g, 512, SMEM_GEMM1>>>(
            (const __half*)pBagF, (const __half*)pWihH,
            (const float*)pBih, (__half*)pXG,
            NIH, NIH, KPAD_IN, KPAD_IN / 64);
    }
    {
        int nw = 2 * BB * KPAD_H / 2;                                                   // 5
        k_zero_h2<<<(nw + 255) / 256, 256>>>((uint32_t*)phA, (uint32_t*)phB, nw);
    }
    k_zero<<<(out_size + 255) / 256, 256>>>(out, (long long)out_size);                  // 6

    // ---- GRU recurrence: one fused launch per step ----
    {
        dim3 g(NI_GRU / 128, BB / 128, 2);   // (8, 32, 2) = 512 blocks
        const __half* hbuf[2] = {(const __half*)phA, (const __half*)phB};
        for (int s = 0; s < TSTEPS; s++) {
            gemm_gru<<<g, 512, SMEM_GEMM>>>(
                hbuf[s & 1],
                (const __half*)pWhhIH, (const __half*)pWhhIL,
                (const float*)pBhh,
                (__half*)(s & 1 ? phA : phB), s);
        }
    }

    // ---- word attention: fused GEMM + tanh.proj score, fused softmax+wv ----
    gemm_score<<<(unsigned)(MM / 128), 512, SMEM_GEMM1>>>(
        (const __half*)pOF, (const __half*)pWwH,
        b_word, proj_word, (float*)pScore, H2, KPAD_W, KPAD_W / 64, NPAD_W / 128);
    k_word_attn<<<BB, 256>>>();

    // ---- sentence attention: fused GEMM + score, then softmax+FC+scatter ----
    gemm_score<<<BB / 128, 512, SMEM_GEMM1>>>(
        (const __half*)pwvF, (const __half*)pWsH,
        b_sent, proj_sent, (float*)pScore2, H2, KPAD_W, KPAD_W / 64, NPAD_W / 128);
    k_sent<<<NBAG, 256>>>(fc_W, fc_b, pairs, out);
}